// round 17
// baseline (speedup 1.0000x reference)
#include <cuda_runtime.h>
#include <math.h>
#include <stdint.h>

#define SEQ 2048
#define HDIM 2048
#define NH 16
#define NKV 4
#define HD 128
#define RD 64
#define NE 16
#define FF 512
#define TKN 4
#define GUW 1024
#define QKVW 3072

#define NSTG 3
#define STG_FLOATS 8192
#define DSMEM_BYTES (NSTG * STG_FLOATS * 4)   // 98304
#define AV_DSMEM (2 * 16384 + 3 * 16384)      // A 2-stage + B 3-stage = 81920

// weight scratch offsets (floats)
#define WQKV_OFF 0
#define WO_OFF   6291456
#define WGU_OFF  10485760
#define WED_OFF  44040192
#define WR_TOT   60817408

// ---------------------------------------------------------------- helpers
static __device__ __forceinline__ uint32_t smem_u32(const void* p) {
    uint32_t a;
    asm("{ .reg .u64 t; cvta.to.shared.u64 t, %1; cvt.u32.u64 %0, t; }"
        : "=r"(a) : "l"(p));
    return a;
}
static __device__ __forceinline__ uint32_t f2tf(float f) {
    uint32_t u; asm("cvt.rna.tf32.f32 %0, %1;" : "=r"(u) : "f"(f)); return u;
}
static __device__ __forceinline__ float f2tf_f(float f) {
    return __uint_as_float(f2tf(f));
}

static __device__ __forceinline__ void mma_tf32(
    float* c, const uint32_t* a, const uint32_t* b)
{
    asm volatile(
        "mma.sync.aligned.m16n8k8.row.col.f32.tf32.tf32.f32 "
        "{%0,%1,%2,%3}, {%4,%5,%6,%7}, {%8,%9}, {%0,%1,%2,%3};"
        : "+f"(c[0]), "+f"(c[1]), "+f"(c[2]), "+f"(c[3])
        : "r"(a[0]), "r"(a[1]), "r"(a[2]), "r"(a[3]), "r"(b[0]), "r"(b[1]));
}

static __device__ __forceinline__ void cp16(uint32_t dst, const float* src, uint32_t sz) {
    asm volatile("cp.async.cg.shared.global [%0], [%1], 16, %2;"
                 :: "r"(dst), "l"(src), "r"(sz));
}
#define CP_COMMIT() asm volatile("cp.async.commit_group;" ::: "memory")
#define CP_WAIT1()  asm volatile("cp.async.wait_group 1;" ::: "memory")

// ---------------------------------------------------------------- scratch
__device__ float g_wr[WR_TOT];                 // tf32 weights: wqkv | wo | wgu | wed
__device__ float g_xn[SEQ * HDIM];
__device__ float g_qkv[SEQ * QKVW];            // q | k | v per row
__device__ float g_scores[(size_t)NH * SEQ * SEQ];
__device__ float g_ao[SEQ * HDIM];
__device__ float g_h1[SEQ * HDIM];
__device__ float g_xf[SEQ * HDIM];
__device__ float g_gu[(size_t)NE * SEQ * GUW];
__device__ float g_hb[NE * SEQ * FF];
__device__ float g_slot[TKN * SEQ * HDIM];
__device__ float g_rowm[NH * SEQ];
__device__ float g_rowinv[NH * SEQ];
__device__ int   g_cnt[NE];
__device__ int   g_tok[NE * SEQ];
__device__ int   g_orow[NE * SEQ];
__device__ float g_wt[NE * SEQ];

// ---------------------------------------------------------------- tf32 GEMM
// C[M,N] = A[M,K] @ op(B) (+resid). Operands pre-rounded to tf32.
// TB=0: B gmem [N,K] (K contiguous rows).  TB=1: B gmem [K,N] (N contiguous rows).
template<int TB>
__global__ void __launch_bounds__(256, 2) tgemm_k(
    const float* __restrict__ A, const float* __restrict__ B,
    float* __restrict__ C, const float* __restrict__ resid,
    int M, int N, int K, int lda, int ldb, int ldc,
    long long sA, long long sB, long long sC, int bzdiv,
    const int* __restrict__ Aidx, const int* __restrict__ Cidx,
    const int* __restrict__ cnt, int causal, int roundC)
{
    int z = blockIdx.z;
    int Mz = cnt ? cnt[z] : M;
    int m0 = blockIdx.y * 128, n0 = blockIdx.x * 128;
    if (m0 >= Mz) return;
    if (causal && n0 > m0 + 127) return;
    int nch = K >> 5;

    extern __shared__ float dsm[];
    uint32_t sb = smem_u32(dsm);

    int tid = threadIdx.x, lane = tid & 31, wid = tid >> 5;
    int wm = wid & 1, wn = wid >> 1;

    const float* Az = A + sA * z;
    const float* Bz = B + sB * (z / bzdiv);
    const int* aidx = Aidx ? Aidx + (size_t)z * SEQ : nullptr;

    int am = tid >> 1;
    int g0 = (tid & 1) * 4;
    const float* asrc; uint32_t avalid;
    {
        int gm = m0 + am;
        if (gm < Mz) {
            int ar = aidx ? aidx[gm] : gm;
            asrc = Az + (size_t)ar * lda + g0 * 4;
            avalid = 16u;
        } else { asrc = Az; avalid = 0u; }
    }
    uint32_t arow7 = (uint32_t)(am & 7);
    uint32_t abyte = (uint32_t)am << 7;

    const float* bsrc0 = nullptr;
    const float* bsrc1 = nullptr;
    int bk = tid >> 3;
    int gb = tid & 7;
    uint32_t bbyte = (uint32_t)bk << 9;
    uint32_t bk3 = (uint32_t)((bk & 3) << 1);
    if (TB == 0) bsrc0 = Bz + (size_t)(n0 + am) * ldb + g0 * 4;
    else         bsrc1 = Bz + (size_t)bk * ldb + n0 + gb * 4;

    float acc[4][4][4];
#pragma unroll
    for (int mf = 0; mf < 4; mf++)
#pragma unroll
        for (int nf = 0; nf < 4; nf++)
#pragma unroll
            for (int r = 0; r < 4; r++) acc[mf][nf][r] = 0.f;

#pragma unroll
    for (int p = 0; p < 2; p++) {
        if (p < nch) {
            uint32_t stg = sb + (uint32_t)p * (STG_FLOATS * 4);
            const float* as = asrc + p * 32;
#pragma unroll
            for (int j = 0; j < 4; j++)
                cp16(stg + abyte + ((uint32_t)((g0 + j) ^ arow7) << 4), as + 4 * j, avalid);
            if (TB == 0) {
                const float* bs = bsrc0 + p * 32;
#pragma unroll
                for (int j = 0; j < 4; j++)
                    cp16(stg + 16384u + abyte + ((uint32_t)((g0 + j) ^ arow7) << 4), bs + 4 * j, 16u);
            } else {
                const float* bs = bsrc1 + (size_t)p * 32 * ldb;
#pragma unroll
                for (int j = 0; j < 4; j++)
                    cp16(stg + 16384u + bbyte + ((uint32_t)((gb + 8 * j) ^ bk3) << 4), bs + 32 * j, 16u);
            }
            CP_COMMIT();
        }
    }

    int c4 = lane & 3;
    int rowA[4], rowB[4], nphysB[4];
#pragma unroll
    for (int mf = 0; mf < 4; mf++) rowA[mf] = wm * 64 + mf * 16 + (lane >> 2);
#pragma unroll
    for (int nf = 0; nf < 4; nf++) {
        rowB[nf] = wn * 32 + nf * 8 + (lane >> 2);
        nphysB[nf] = rowB[nf] ^ (c4 << 3);
    }

    for (int i = 0; i < nch; i++) {
        CP_WAIT1();
        __syncthreads();

        if (i + 2 < nch) {
            uint32_t stg = sb + (uint32_t)((i + 2) % NSTG) * (STG_FLOATS * 4);
            const float* as = asrc + (i + 2) * 32;
#pragma unroll
            for (int j = 0; j < 4; j++)
                cp16(stg + abyte + ((uint32_t)((g0 + j) ^ arow7) << 4), as + 4 * j, avalid);
            if (TB == 0) {
                const float* bs = bsrc0 + (i + 2) * 32;
#pragma unroll
                for (int j = 0; j < 4; j++)
                    cp16(stg + 16384u + abyte + ((uint32_t)((g0 + j) ^ arow7) << 4), bs + 4 * j, 16u);
            } else {
                const float* bs = bsrc1 + (size_t)(i + 2) * 32 * ldb;
#pragma unroll
                for (int j = 0; j < 4; j++)
                    cp16(stg + 16384u + bbyte + ((uint32_t)((gb + 8 * j) ^ bk3) << 4), bs + 32 * j, 16u);
            }
            CP_COMMIT();
        }

        const uint32_t* sA32 = reinterpret_cast<const uint32_t*>(dsm + (i % NSTG) * STG_FLOATS);
        const uint32_t* sB32 = sA32 + 4096;

#pragma unroll
        for (int ks = 0; ks < 4; ks++) {
            int g = ks * 2;
            uint32_t af[4][4], bf[4][2];
#pragma unroll
            for (int mf = 0; mf < 4; mf++) {
                int r = rowA[mf], r8 = r + 8;
                af[mf][0] = sA32[(r  << 5) + (((g    ) ^ (r  & 7)) << 2) + c4];
                af[mf][1] = sA32[(r8 << 5) + (((g    ) ^ (r8 & 7)) << 2) + c4];
                af[mf][2] = sA32[(r  << 5) + (((g + 1) ^ (r  & 7)) << 2) + c4];
                af[mf][3] = sA32[(r8 << 5) + (((g + 1) ^ (r8 & 7)) << 2) + c4];
            }
            if (TB == 0) {
#pragma unroll
                for (int nf = 0; nf < 4; nf++) {
                    int r = rowB[nf];
                    bf[nf][0] = sB32[(r << 5) + (((g    ) ^ (r & 7)) << 2) + c4];
                    bf[nf][1] = sB32[(r << 5) + (((g + 1) ^ (r & 7)) << 2) + c4];
                }
            } else {
#pragma unroll
                for (int nf = 0; nf < 4; nf++) {
                    int base = (ks * 8 + c4) * 128 + nphysB[nf];
                    bf[nf][0] = sB32[base];
                    bf[nf][1] = sB32[base + 512];
                }
            }
#pragma unroll
            for (int mf = 0; mf < 4; mf++)
#pragma unroll
                for (int nf = 0; nf < 4; nf++)
                    mma_tf32(acc[mf][nf], af[mf], bf[nf]);
        }
    }

    float* Cz = C + sC * z;
    const int* cidx = Cidx ? Cidx + (size_t)z * SEQ : nullptr;
#pragma unroll
    for (int mf = 0; mf < 4; mf++) {
#pragma unroll
        for (int half = 0; half < 2; half++) {
            int gm = m0 + wm * 64 + mf * 16 + (lane >> 2) + half * 8;
            if (gm >= Mz) continue;
            int cr = cidx ? cidx[gm] : gm;
            float* crow = Cz + (size_t)cr * ldc;
            const float* rrow = resid ? resid + (size_t)cr * ldc : nullptr;
#pragma unroll
            for (int nf = 0; nf < 4; nf++) {
                int gc = n0 + wn * 32 + nf * 8 + (lane & 3) * 2;
                float2 v;
                v.x = acc[mf][nf][half * 2 + 0];
                v.y = acc[mf][nf][half * 2 + 1];
                if (rrow) { v.x += rrow[gc]; v.y += rrow[gc + 1]; }
                if (roundC) { v.x = f2tf_f(v.x); v.y = f2tf_f(v.y); }
                *reinterpret_cast<float2*>(crow + gc) = v;
            }
        }
    }
}

// ---------------------------------------------------------------- fused AV
// ao[:, 128h..] += probs(h) @ V(h/4); probs computed on the fly from raw
// scores + per-row (m, inv) stats. A staged via LDG+exp+STS, B via cp.async.
__global__ void __launch_bounds__(256, 2) avgemm_k(
    const float* __restrict__ S, const float* __restrict__ V,
    float* __restrict__ C, const float* __restrict__ rowm,
    const float* __restrict__ rowinv)
{
    int z = blockIdx.z;
    int m0 = blockIdx.y * 128;
    int nch = (m0 + 128) >> 5;
    const float scale = 0.08838834764831845f;

    extern __shared__ float dsm[];
    uint32_t sb = smem_u32(dsm);
    uint32_t sbB = sb + 32768u;

    int tid = threadIdx.x, lane = tid & 31, wid = tid >> 5;
    int wm = wid & 1, wn = wid >> 1;

    const float* Sz = S + (size_t)z * SEQ * SEQ;
    const float* Bz = V + (size_t)128 * (z >> 2);

    int am = tid >> 1;
    int g0 = (tid & 1) * 4;
    int grow = m0 + am;
    const float* arow = Sz + (size_t)grow * SEQ + g0 * 4;
    float mrow = rowm[z * SEQ + grow];
    float vinv = rowinv[z * SEQ + grow];
    uint32_t arow7 = (uint32_t)(am & 7);
    uint32_t abyte = (uint32_t)am << 7;

    int bk = tid >> 3;
    int gb = tid & 7;
    const float* bsrc = Bz + (size_t)bk * QKVW + gb * 4;
    uint32_t bbyte = (uint32_t)bk << 9;
    uint32_t bk3 = (uint32_t)((bk & 3) << 1);

    float acc[4][4][4];
#pragma unroll
    for (int mf = 0; mf < 4; mf++)
#pragma unroll
        for (int nf = 0; nf < 4; nf++)
#pragma unroll
            for (int r = 0; r < 4; r++) acc[mf][nf][r] = 0.f;

    // B prologue: chunks 0,1 (nch >= 4 always)
#pragma unroll
    for (int p = 0; p < 2; p++) {
        uint32_t stg = sbB + (uint32_t)p * 16384u;
        const float* bs = bsrc + (size_t)p * 32 * QKVW;
#pragma unroll
        for (int j = 0; j < 4; j++)
            cp16(stg + bbyte + ((uint32_t)((gb + 8 * j) ^ bk3) << 4), bs + 32 * j, 16u);
        CP_COMMIT();
    }
    // A prefetch chunk 0
    float4 rA[4];
#pragma unroll
    for (int j = 0; j < 4; j++)
        rA[j] = *reinterpret_cast<const float4*>(arow + 4 * j);

    int c4 = lane & 3;
    int rowA[4], rowB[4], nphysB[4];
#pragma unroll
    for (int mf = 0; mf < 4; mf++) rowA[mf] = wm * 64 + mf * 16 + (lane >> 2);
#pragma unroll
    for (int nf = 0; nf < 4; nf++) {
        rowB[nf] = wn * 32 + nf * 8 + (lane >> 2);
        nphysB[nf] = rowB[nf] ^ (c4 << 3);
    }

    for (int i = 0; i < nch; i++) {
        CP_WAIT1();
        __syncthreads();   // compute i-1 done: safe to overwrite A stage i&1 / B stage (i+2)%3

        // STS A chunk i with probs transform
        {
            uint32_t Ast = sb + (uint32_t)(i & 1) * 16384u;
            int cb = i * 32 + g0 * 4;
#pragma unroll
            for (int j = 0; j < 4; j++) {
                float s0 = rA[j].x, s1 = rA[j].y, s2 = rA[j].z, s3 = rA[j].w;
                int c0 = cb + 4 * j;
                uint32_t p0 = (c0     <= grow) ? f2tf(expf(s0 * scale - mrow) * vinv) : 0u;
                uint32_t p1 = (c0 + 1 <= grow) ? f2tf(expf(s1 * scale - mrow) * vinv) : 0u;
                uint32_t p2 = (c0 + 2 <= grow) ? f2tf(expf(s2 * scale - mrow) * vinv) : 0u;
                uint32_t p3 = (c0 + 3 <= grow) ? f2tf(expf(s3 * scale - mrow) * vinv) : 0u;
                asm volatile("st.shared.v4.b32 [%0], {%1,%2,%3,%4};"
                             :: "r"(Ast + abyte + ((uint32_t)((g0 + j) ^ arow7) << 4)),
                                "r"(p0), "r"(p1), "r"(p2), "r"(p3));
            }
        }
        // issue B chunk i+2
        if (i + 2 < nch) {
            uint32_t stg = sbB + (uint32_t)((i + 2) % 3) * 16384u;
            const float* bs = bsrc + (size_t)(i + 2) * 32 * QKVW;
#pragma unroll
            for (int j = 0; j < 4; j++)
                cp16(stg + bbyte + ((uint32_t)((gb + 8 * j) ^ bk3) << 4), bs + 32 * j, 16u);
            CP_COMMIT();
        }
        // prefetch A chunk i+1
        if (i + 1 < nch) {
            const float* as = arow + (i + 1) * 32;
#pragma unroll
            for (int j = 0; j < 4; j++)
                rA[j] = *reinterpret_cast<const float4*>(as + 4 * j);
        }
        __syncthreads();   // A stage i visible

        const uint32_t* sA32 = reinterpret_cast<const uint32_t*>(dsm + (i & 1) * 4096);
        const uint32_t* sB32 = reinterpret_cast<const uint32_t*>(dsm + 8192 + (i % 3) * 4096);

#pragma unroll
        for (int ks = 0; ks < 4; ks++) {
            int g = ks * 2;
            uint32_t af[4][4], bf[4][2];
#pragma unroll
            for (int mf = 0; mf < 4; mf++) {
                int r = rowA[mf], r8 = r + 8;
                af[mf][0] = sA32[(r  << 5) + (((g    ) ^ (r  & 7)) << 2) + c4];
                af[mf][1] = sA32[(r8 << 5) + (((g    ) ^ (r8 & 7)) << 2) + c4];
                af[mf][2] = sA32[(r  << 5) + (((g + 1) ^ (r  & 7)) << 2) + c4];
                af[mf][3] = sA32[(r8 << 5) + (((g + 1) ^ (r8 & 7)) << 2) + c4];
            }
#pragma unroll
            for (int nf = 0; nf < 4; nf++) {
                int base = (ks * 8 + c4) * 128 + nphysB[nf];
                bf[nf][0] = sB32[base];
                bf[nf][1] = sB32[base + 512];
            }
#pragma unroll
            for (int mf = 0; mf < 4; mf++)
#pragma unroll
                for (int nf = 0; nf < 4; nf++)
                    mma_tf32(acc[mf][nf], af[mf], bf[nf]);
        }
    }

    float* Cz = C + 128 * z;
#pragma unroll
    for (int mf = 0; mf < 4; mf++) {
#pragma unroll
        for (int half = 0; half < 2; half++) {
            int gm = m0 + wm * 64 + mf * 16 + (lane >> 2) + half * 8;
            float* crow = Cz + (size_t)gm * HDIM;
#pragma unroll
            for (int nf = 0; nf < 4; nf++) {
                int gc = wn * 32 + nf * 8 + (lane & 3) * 2;
                float2 v;
                v.x = f2tf_f(acc[mf][nf][half * 2 + 0]);
                v.y = f2tf_f(acc[mf][nf][half * 2 + 1]);
                *reinterpret_cast<float2*>(crow + gc) = v;
            }
        }
    }
}

// ---------------------------------------------------------------- round copies
__global__ void roundcpy_k(const float4* __restrict__ in, float4* __restrict__ out)
{
    size_t i = (size_t)blockIdx.x * 256 + threadIdx.x;
    float4 v = in[i];
    v.x = f2tf_f(v.x); v.y = f2tf_f(v.y); v.z = f2tf_f(v.z); v.w = f2tf_f(v.w);
    out[i] = v;
}

// strided: out[z][row][outld] <- round(in[z][row][incols]); units = float4
__global__ void roundcpy2_k(const float4* __restrict__ in, float4* __restrict__ out,
                            int inc4, int outld4, long long inz4, long long outz4)
{
    int z = blockIdx.y;
    int f = blockIdx.x * 256 + threadIdx.x;
    int row = f / inc4, c = f - row * inc4;
    float4 v = in[inz4 * z + f];
    v.x = f2tf_f(v.x); v.y = f2tf_f(v.y); v.z = f2tf_f(v.z); v.w = f2tf_f(v.w);
    out[outz4 * z + (size_t)row * outld4 + c] = v;
}

// ---------------------------------------------------------------- aux kernels
__global__ void rmsnorm_k(const float* __restrict__ x, const float* __restrict__ w,
                          float* __restrict__ o, float* __restrict__ ofull)
{
    int t = blockIdx.x, tid = threadIdx.x;
    const float* xr = x + (size_t)t * HDIM;
    float s = 0.f;
    for (int h = tid; h < HDIM; h += 256) { float v = xr[h]; s += v * v; }
    __shared__ float red[256];
    red[tid] = s; __syncthreads();
    for (int st = 128; st > 0; st >>= 1) {
        if (tid < st) red[tid] += red[tid + st];
        __syncthreads();
    }
    float inv = rsqrtf(red[0] / (float)HDIM + 1e-6f);
    float* orow = o + (size_t)t * HDIM;
    float* frow = ofull ? ofull + (size_t)t * HDIM : nullptr;
    for (int h = tid; h < HDIM; h += 256) {
        float v = w[h] * xr[h] * inv;
        orow[h] = f2tf_f(v);
        if (frow) frow[h] = v;
    }
}

__global__ void rope_k(float* __restrict__ x, int ld, const float* __restrict__ cosb,
                       const float* __restrict__ sinb)
{
    int s = blockIdx.x, h = blockIdx.y, d = threadIdx.x;
    float* r = x + (size_t)s * ld + h * HD;
    float v = r[d];
    float w = (d < 64) ? r[d ^ 32] : 0.f;
    __syncthreads();
    if (d < 32)      r[d] = f2tf_f(v * cosb[s * RD + d] - w * sinb[s * RD + d]);
    else if (d < 64) r[d] = f2tf_f(v * cosb[s * RD + d] + w * sinb[s * RD + d]);
}

__global__ void rowstats_k(const float* __restrict__ sc, const float* __restrict__ sink,
                           float* __restrict__ rowm, float* __restrict__ rowinv)
{
    int i = blockIdx.x, h = blockIdx.y, tid = threadIdx.x;
    const float* row = sc + ((size_t)h * SEQ + i) * (size_t)SEQ;
    const float scale = 0.08838834764831845f;
    __shared__ float red[256];

    float lv[8];
    float m = -1e30f;
#pragma unroll
    for (int c = 0; c < 8; c++) {
        int j = tid + (c << 8);
        if (j <= i) { float v = row[j] * scale; lv[c] = v; m = fmaxf(m, v); }
    }
    red[tid] = m; __syncthreads();
    for (int st = 128; st > 0; st >>= 1) {
        if (tid < st) red[tid] = fmaxf(red[tid], red[tid + st]);
        __syncthreads();
    }
    m = red[0]; __syncthreads();

    float s = 0.f;
#pragma unroll
    for (int c = 0; c < 8; c++) {
        int j = tid + (c << 8);
        if (j <= i) s += expf(lv[c] - m);
    }
    red[tid] = s; __syncthreads();
    for (int st = 128; st > 0; st >>= 1) {
        if (tid < st) red[tid] += red[tid + st];
        __syncthreads();
    }
    if (tid == 0) {
        rowm[h * SEQ + i] = m;
        rowinv[h * SEQ + i] = 1.f / (red[0] + expf(sink[h] - m));
    }
}

__global__ void zero_cnt_k(int* cnt) { if (threadIdx.x < NE) cnt[threadIdx.x] = 0; }

__global__ void router_k(const float* __restrict__ xf, const float* __restrict__ gw,
                         const float* __restrict__ gbias, int* cnt, int* tok,
                         int* orow, float* wt)
{
    int t = blockIdx.x, tid = threadIdx.x;
    int lane = tid & 31, wid = tid >> 5;
    __shared__ float logits[NE];
    const float* xr = xf + (size_t)t * HDIM;

    for (int e = wid; e < NE; e += 8) {
        const float* gr = gw + (size_t)e * HDIM;
        float p = 0.f;
        for (int hh = lane; hh < HDIM; hh += 32) p += xr[hh] * gr[hh];
        for (int off = 16; off > 0; off >>= 1) p += __shfl_down_sync(0xffffffffu, p, off);
        if (lane == 0) logits[e] = p;
    }
    __syncthreads();

    if (tid == 0) {
        float sg[NE], sfc[NE];
        for (int e = 0; e < NE; e++) {
            sg[e] = 1.f / (1.f + expf(-logits[e]));
            sfc[e] = sg[e] + gbias[e];
        }
        float gs[4];
        for (int g = 0; g < 4; g++) {
            float m1 = -1e30f, m2 = -1e30f;
            for (int j = 0; j < 4; j++) {
                float v = sfc[g * 4 + j];
                if (v > m1) { m2 = m1; m1 = v; } else if (v > m2) m2 = v;
            }
            gs[g] = m1 + m2;
        }
        int g1 = 0;
        for (int g = 1; g < 4; g++) if (gs[g] > gs[g1]) g1 = g;
        int g2 = -1;
        for (int g = 0; g < 4; g++) {
            if (g == g1) continue;
            if (g2 < 0 || gs[g] > gs[g2]) g2 = g;
        }
        bool allow[NE];
        for (int e = 0; e < NE; e++) { int g = e >> 2; allow[e] = (g == g1 || g == g2); }

        int idx[TKN]; float tws[TKN]; float sum = 0.f;
        bool used[NE] = {};
        for (int j = 0; j < TKN; j++) {
            int bi = -1; float bv = -1e30f;
            for (int e = 0; e < NE; e++)
                if (allow[e] && !used[e] && sfc[e] > bv) { bv = sfc[e]; bi = e; }
            used[bi] = true; idx[j] = bi; tws[j] = sg[bi]; sum += tws[j];
        }
        float invs = 2.5f / (sum + 1e-20f);
        for (int j = 0; j < TKN; j++) {
            int e = idx[j];
            int pos = atomicAdd(&cnt[e], 1);
            tok[e * SEQ + pos]  = t;
            orow[e * SEQ + pos] = j * SEQ + t;
            wt[e * SEQ + pos]   = tws[j] * invs;
        }
    }
}

__global__ void silu_k(const float* __restrict__ gu, float* __restrict__ hb,
                       const float* __restrict__ wt, const int* __restrict__ cnt)
{
    int e = blockIdx.y, r = blockIdx.x;
    if (r >= cnt[e]) return;
    float w = wt[e * SEQ + r];
    const float* g = gu + ((size_t)e * SEQ + r) * GUW;
    float* o = hb + ((size_t)e * SEQ + r) * FF;
    for (int f = threadIdx.x; f < FF; f += 256) {
        float gv = g[f], uv = g[FF + f];
        float sig = 1.f / (1.f + expf(-gv));
        o[f] = f2tf_f(gv * sig * uv * w);
    }
}

__global__ void final_k(const float* __restrict__ h1, const float* __restrict__ slot,
                        float* __restrict__ out)
{
    size_t i = (size_t)blockIdx.x * 256 + threadIdx.x;
    const size_t NTOT = (size_t)SEQ * HDIM;
    out[i] = h1[i] + slot[i] + slot[NTOT + i] + slot[2 * NTOT + i] + slot[3 * NTOT + i];
}

// ---------------------------------------------------------------- launch
extern "C" void kernel_launch(void* const* d_in, const int* in_sizes, int n_in,
                              void* d_out, int out_size)
{
    const float* x      = (const float*)d_in[0];
    const float* cosb   = (const float*)d_in[1];
    const float* sinb   = (const float*)d_in[2];
    const float* ln1    = (const float*)d_in[3];
    const float* ln2    = (const float*)d_in[4];
    const float* Wq     = (const float*)d_in[5];
    const float* Wk     = (const float*)d_in[6];
    const float* Wv     = (const float*)d_in[7];
    const float* Wo     = (const float*)d_in[8];
    const float* sink   = (const float*)d_in[9];
    const float* gate_w = (const float*)d_in[10];
    const float* gate_b = (const float*)d_in[11];
    const float* Weg    = (const float*)d_in[12];
    const float* Weu    = (const float*)d_in[13];
    const float* Wed    = (const float*)d_in[14];
    float* out = (float*)d_out;

    cudaFuncSetAttribute(tgemm_k<0>, cudaFuncAttributeMaxDynamicSharedMemorySize, DSMEM_BYTES);
    cudaFuncSetAttribute(tgemm_k<1>, cudaFuncAttributeMaxDynamicSharedMemorySize, DSMEM_BYTES);
    cudaFuncSetAttribute(avgemm_k,   cudaFuncAttributeMaxDynamicSharedMemorySize, AV_DSMEM);

    void *p_wr, *p_xn, *p_qkv, *p_sc, *p_ao, *p_h1, *p_xf,
         *p_gu, *p_hb, *p_slot, *p_rm, *p_ri, *p_cnt, *p_tok, *p_orow, *p_wt;
    cudaGetSymbolAddress(&p_wr, g_wr);
    cudaGetSymbolAddress(&p_xn, g_xn);
    cudaGetSymbolAddress(&p_qkv, g_qkv);
    cudaGetSymbolAddress(&p_sc, g_scores);
    cudaGetSymbolAddress(&p_ao, g_ao);
    cudaGetSymbolAddress(&p_h1, g_h1);
    cudaGetSymbolAddress(&p_xf, g_xf);
    cudaGetSymbolAddress(&p_gu, g_gu);
    cudaGetSymbolAddress(&p_hb, g_hb);
    cudaGetSymbolAddress(&p_slot, g_slot);
    cudaGetSymbolAddress(&p_rm, g_rowm);
    cudaGetSymbolAddress(&p_ri, g_rowinv);
    cudaGetSymbolAddress(&p_cnt, g_cnt);
    cudaGetSymbolAddress(&p_tok, g_tok);
    cudaGetSymbolAddress(&p_orow, g_orow);
    cudaGetSymbolAddress(&p_wt, g_wt);

    float* wr   = (float*)p_wr;
    float* xn   = (float*)p_xn;
    float* qkv  = (float*)p_qkv;
    float* sc   = (float*)p_sc;
    float* ao   = (float*)p_ao;
    float* h1   = (float*)p_h1;
    float* xf   = (float*)p_xf;
    float* gu   = (float*)p_gu;
    float* hb   = (float*)p_hb;
    float* slot = (float*)p_slot;
    float* rowm = (float*)p_rm;
    float* rowinv = (float*)p_ri;
    int* cnt = (int*)p_cnt; int* tok = (int*)p_tok; int* orow = (int*)p_orow;
    float* wt = (float*)p_wt;

    zero_cnt_k<<<1, 32>>>(cnt);

    // --- tf32-round weights into native-layout blocks (Q|K|V and G|U interleaved) ---
    roundcpy2_k<<<dim3(4096, 1), 256>>>((const float4*)Wq, (float4*)(wr + WQKV_OFF),
        512, 768, 0, 0);
    roundcpy2_k<<<dim3(1024, 1), 256>>>((const float4*)Wk, (float4*)(wr + WQKV_OFF + 2048),
        128, 768, 0, 0);
    roundcpy2_k<<<dim3(1024, 1), 256>>>((const float4*)Wv, (float4*)(wr + WQKV_OFF + 2560),
        128, 768, 0, 0);
    roundcpy_k<<<4194304 / 1024, 256>>>((const float4*)Wo, (float4*)(wr + WO_OFF));
    roundcpy2_k<<<dim3(1024, NE), 256>>>((const float4*)Weg, (float4*)(wr + WGU_OFF),
        128, 256, 262144, 524288);
    roundcpy2_k<<<dim3(1024, NE), 256>>>((const float4*)Weu, (float4*)(wr + WGU_OFF + 512),
        128, 256, 262144, 524288);
    roundcpy_k<<<16777216 / 1024, 256>>>((const float4*)Wed, (float4*)(wr + WED_OFF));

    rmsnorm_k<<<SEQ, 256>>>(x, ln1, xn, nullptr);

    // fused QKV projection: qkv[s] = [q(2048) | k(512) | v(512)]
    tgemm_k<1><<<dim3(QKVW / 128, 16, 1), 256, DSMEM_BYTES>>>(
        xn, wr + WQKV_OFF, qkv, nullptr, SEQ, QKVW, 2048, 2048, QKVW, QKVW,
        0, 0, 0, 1, nullptr, nullptr, nullptr, 0, 1);

    rope_k<<<dim3(SEQ, NH), 128>>>(qkv, QKVW, cosb, sinb);
    rope_k<<<dim3(SEQ, NKV), 128>>>(qkv + 2048, QKVW, cosb, sinb);

    // scores[h] = q[h] @ k[h/4]^T
    tgemm_k<0><<<dim3(16, 16, NH), 256, DSMEM_BYTES>>>(
        qkv, qkv + 2048, sc, nullptr, SEQ, SEQ, HD, QKVW, QKVW, SEQ,
        128, 128, (long long)SEQ * SEQ, NH / NKV,
        nullptr, nullptr, nullptr, 1, 0);

    // per-row max + denom (sink included); probs never materialized
    rowstats_k<<<dim3(SEQ, NH), 256>>>(sc, sink, rowm, rowinv);

    // fused exp + P@V
    avgemm_k<<<dim3(1, 16, NH), 256, AV_DSMEM>>>(sc, qkv + 2560, ao, rowm, rowinv);

    // h1 = ao @ Wo + x
    tgemm_k<1><<<dim3(16, 16, 1), 256, DSMEM_BYTES>>>(
        ao, wr + WO_OFF, h1, x, SEQ, 2048, 2048, 2048, 2048, 2048,
        0, 0, 0, 1, nullptr, nullptr, nullptr, 0, 0);

    // xf (tf32 for GEMM) + xn reused as unrounded copy for the router
    rmsnorm_k<<<SEQ, 256>>>(h1, ln2, xf, xn);
    router_k<<<SEQ, 256>>>(xn, gate_w, gate_b, cnt, tok, orow, wt);

    // fused gate|up per expert (row-gathered A)
    tgemm_k<1><<<dim3(GUW / 128, 16, NE), 256, DSMEM_BYTES>>>(
        xf, wr + WGU_OFF, gu, nullptr, SEQ, GUW, 2048, 2048, GUW, GUW,
        0, (long long)2048 * GUW, (long long)SEQ * GUW, 1,
        tok, nullptr, cnt, 0, 0);

    silu_k<<<dim3(SEQ, NE), 256>>>(gu, hb, wt, cnt);

    // down projection, scattered to per-(slot,token) rows
    tgemm_k<1><<<dim3(16, 16, NE), 256, DSMEM_BYTES>>>(
        hb, wr + WED_OFF, slot, nullptr, SEQ, 2048, FF, FF, 2048, 2048,
        (long long)SEQ * FF, (long long)FF * 2048, 0, 1,
        nullptr, orow, cnt, 0, 0);

    final_k<<<(SEQ * HDIM) / 256, 256>>>(h1, slot, out);
}